// round 5
// baseline (speedup 1.0000x reference)
#include <cuda_runtime.h>
#include <math.h>

#define B   64
#define S   96
#define E   300
#define D   512
#define H   256
#define SEL 128
#define G5  1280   // 5*H
#define MLPD 1024
#define NC  3

typedef unsigned long long ull;

// ---- static device scratch (no allocs allowed) ----
__device__ __align__(16) float g_states[B][S][D];     // 12.6 MB, L2-resident
__device__ float g_logits0[B][S - 1];
__device__ float g_hroot[B][H];
__device__ float g_x1[B][MLPD];
__device__ float g_x2[B][MLPD];

__device__ __forceinline__ float sigf(float x) { return 1.0f / (1.0f + expf(-x)); }

// packed dual-fp32 fma: per-lane round-to-nearest, bit-identical to __fmaf_rn
__device__ __forceinline__ ull fma2(ull a, ull b, ull c) {
    ull d;
    asm("fma.rn.f32x2 %0, %1, %2, %3;" : "=l"(d) : "l"(a), "l"(b), "l"(c));
    return d;
}
__device__ __forceinline__ ull pack2(float x, float y) {
    ull d;
    asm("mov.b64 %0, {%1, %2};" : "=l"(d) : "f"(x), "f"(y));
    return d;
}
__device__ __forceinline__ float lo32(ull v) { return __uint_as_float((unsigned)(v & 0xffffffffull)); }
__device__ __forceinline__ float hi32(ull v) { return __uint_as_float((unsigned)(v >> 32)); }

// Shared pair-logit piece: thread j's partial = tanh(preact_j) * Ws2[j].
// Used identically by initsel and the scan's phase 5 so cached and
// recomputed logits are bit-identical.
__device__ __forceinline__ float pair_logit_partial(
    const float* __restrict__ hL, const float* __restrict__ hR,
    const float* __restrict__ Ws1, const float* __restrict__ bs1,
    const float* __restrict__ Ws2, int j)
{
    float a[8];
#pragma unroll
    for (int m = 0; m < 8; m++) a[m] = 0.0f;
    const float* wp = Ws1 + j;
    for (int k = 0; k < 64; k++) {
#pragma unroll
        for (int m = 0; m < 4; m++)
            a[m] = __fmaf_rn(hL[m * 64 + k], wp[(m * 64 + k) * SEL], a[m]);
#pragma unroll
        for (int m = 0; m < 4; m++)
            a[4 + m] = __fmaf_rn(hR[m * 64 + k], wp[(256 + m * 64 + k) * SEL], a[4 + m]);
    }
    float s = __fadd_rn(__fadd_rn(__fadd_rn(a[0], a[1]), __fadd_rn(a[2], a[3])),
                        __fadd_rn(__fadd_rn(a[4], a[5]), __fadd_rn(a[6], a[7])));
    s = __fadd_rn(s, bs1[j]);
    return __fmul_rn(tanhf(s), Ws2[j]);
}

// ======================================================================
// Kernel 1: encode  states[b][s][:] = embed[sent[b][s]] @ W_enc + b_enc
// ======================================================================
__global__ void encode_kernel(const int* __restrict__ sent,
                              const float* __restrict__ emb,
                              const float* __restrict__ Wenc,
                              const float* __restrict__ benc) {
    __shared__ float xs[8][E];
    __shared__ int tok[8];
    int row0 = blockIdx.x * 8;
    int tid = threadIdx.x;
    if (tid < 8) tok[tid] = sent[row0 + tid];
    __syncthreads();
    for (int i = tid; i < 8 * E; i += 128) {
        int r = i / E, k = i - r * E;
        xs[r][k] = emb[(long)tok[r] * E + k];
    }
    __syncthreads();
    int c = tid * 4;
    float4 acc[8];
#pragma unroll
    for (int r = 0; r < 8; r++) acc[r] = make_float4(0.f, 0.f, 0.f, 0.f);
    for (int k = 0; k < E; k++) {
        float4 w = *(const float4*)&Wenc[k * D + c];
#pragma unroll
        for (int r = 0; r < 8; r++) {
            float xv = xs[r][k];
            acc[r].x = __fmaf_rn(xv, w.x, acc[r].x);
            acc[r].y = __fmaf_rn(xv, w.y, acc[r].y);
            acc[r].z = __fmaf_rn(xv, w.z, acc[r].z);
            acc[r].w = __fmaf_rn(xv, w.w, acc[r].w);
        }
    }
    float4 bv = *(const float4*)&benc[c];
#pragma unroll
    for (int r = 0; r < 8; r++) {
        acc[r].x = __fadd_rn(acc[r].x, bv.x);
        acc[r].y = __fadd_rn(acc[r].y, bv.y);
        acc[r].z = __fadd_rn(acc[r].z, bv.z);
        acc[r].w = __fadd_rn(acc[r].w, bv.w);
        int gr = row0 + r;
        int b = gr / S, s = gr - b * S;
        *(float4*)&g_states[b][s][c] = acc[r];
    }
}

// ======================================================================
// Kernel 2: initial pair logits (95 per batch)
// ======================================================================
__global__ void initsel_kernel(const float* __restrict__ Ws1,
                               const float* __restrict__ bs1,
                               const float* __restrict__ Ws2,
                               const float* __restrict__ bs2) {
    __shared__ float hs[17][H];
    __shared__ float red[4];
    int b = blockIdx.y;
    int p0 = blockIdx.x * 16;
    int tid = threadIdx.x;
    int nrows = min(17, S - p0);
    for (int i = tid; i < nrows * H; i += 128) {
        int r = i >> 8, k = i & (H - 1);
        hs[r][k] = g_states[b][p0 + r][H + k];
    }
    __syncthreads();
    int npairs = min(16, (S - 1) - p0);
    for (int p = 0; p < npairs; p++) {
        float y = pair_logit_partial(hs[p], hs[p + 1], Ws1, bs1, Ws2, tid);
        for (int o = 16; o; o >>= 1)
            y = __fadd_rn(y, __shfl_xor_sync(0xffffffffu, y, o));
        if ((tid & 31) == 0) red[tid >> 5] = y;
        __syncthreads();
        if (tid == 0)
            g_logits0[b][p0 + p] =
                __fadd_rn(__fadd_rn(__fadd_rn(red[0], red[1]), __fadd_rn(red[2], red[3])), bs2[0]);
        __syncthreads();
    }
}

// ======================================================================
// Kernel 3: the 95-step scan. 32 CTAs, 2 batches per CTA, 640 threads.
// ======================================================================
#define BD 640
__global__ void __launch_bounds__(BD, 1)
scan_kernel(const float* __restrict__ Wc,  const float* __restrict__ bc,
            const float* __restrict__ Ws1, const float* __restrict__ bs1,
            const float* __restrict__ Ws2, const float* __restrict__ bs2) {
    __shared__ ull   xs2[2][D];       // compose inputs, packed (x,x)
    __shared__ float xsel[4][D];      // staged sel inputs (2 batches x 2 pairs)
    __shared__ float as_[2][G5];      // raw gates
    __shared__ float lg[2][S];        // cached pair logits
    __shared__ int   pm[2][S];        // slot permutation
    __shared__ int   selidx[2];
    __shared__ int   sL[2], sR[2];
    __shared__ float red[4][4];
    __shared__ float amax[2][4];
    __shared__ int   amaxi[2][4];

    int tid = threadIdx.x;
    int cta = blockIdx.x;
    int gb0 = cta * 2;

    for (int i = tid; i < 2 * (S - 1); i += BD) {
        int b = i / (S - 1), j = i - b * (S - 1);
        lg[b][j] = g_logits0[gb0 + b][j];
    }
    for (int i = tid; i < 2 * S; i += BD) {
        int b = i / S, j = i - b * S;
        pm[b][j] = j;
    }
    __syncthreads();

    for (int t = 0; t < S - 1; t++) {
        int n = S - t;        // active items
        int np = n - 1;       // active pairs

        // ---- Phase 0: per-batch argmax (first occurrence on ties) ----
        if (tid < 256) {
            int b = tid >> 7, lt = tid & 127;
            float best = -1e30f; int bi = 0;
            for (int j = lt; j < np; j += 128) {
                float v = lg[b][j];
                if (v > best) { best = v; bi = j; }
            }
            for (int o = 16; o; o >>= 1) {
                float ov = __shfl_xor_sync(0xffffffffu, best, o);
                int   oi = __shfl_xor_sync(0xffffffffu, bi, o);
                if (ov > best || (ov == best && oi < bi)) { best = ov; bi = oi; }
            }
            if ((lt & 31) == 0) { amax[b][lt >> 5] = best; amaxi[b][lt >> 5] = bi; }
        }
        __syncthreads();
        if (tid < 2) {
            int b = tid;
            float best = amax[b][0]; int bi = amaxi[b][0];
            for (int w = 1; w < 4; w++) {
                float v = amax[b][w]; int i2 = amaxi[b][w];
                if (v > best || (v == best && i2 < bi)) { best = v; bi = i2; }
            }
            selidx[b] = bi;
            sL[b] = pm[b][bi];
            sR[b] = pm[b][bi + 1];
        }
        __syncthreads();

        // ---- Phase 1: stage packed x = [h(left), h(right)] for both batches ----
        for (int i = tid; i < 2 * D; i += BD) {
            int b = i >> 9, k = i & (D - 1);
            int slot = (k < H) ? sL[b] : sR[b];
            int col  = (k < H) ? (H + k) : k;
            float xv = g_states[gb0 + b][slot][col];
            xs2[b][k] = pack2(xv, xv);
        }
        __syncthreads();

        // ---- Phase 2: compose GEMV, 2 cols/thread, packed dual-fp32 FMA,
        //      4-way k-split accumulators (same rounding as R3) ----
        {
            int c = tid * 2;
            ull a0[4], a1[4];
#pragma unroll
            for (int m = 0; m < 4; m++) { a0[m] = 0ull; a1[m] = 0ull; }
            const float* wp = Wc + c;
            for (int k = 0; k < 128; k++) {
#pragma unroll
                for (int m = 0; m < 4; m++) {
                    int idx = m * 128 + k;
                    ull w = *(const ull*)(wp + (size_t)idx * G5);
                    a0[m] = fma2(w, xs2[0][idx], a0[m]);
                    a1[m] = fma2(w, xs2[1][idx], a1[m]);
                }
            }
            float2 bv = *(const float2*)&bc[c];
            as_[0][c]     = __fadd_rn(__fadd_rn(__fadd_rn(lo32(a0[0]), lo32(a0[1])), __fadd_rn(lo32(a0[2]), lo32(a0[3]))), bv.x);
            as_[0][c + 1] = __fadd_rn(__fadd_rn(__fadd_rn(hi32(a0[0]), hi32(a0[1])), __fadd_rn(hi32(a0[2]), hi32(a0[3]))), bv.y);
            as_[1][c]     = __fadd_rn(__fadd_rn(__fadd_rn(lo32(a1[0]), lo32(a1[1])), __fadd_rn(lo32(a1[2]), lo32(a1[3]))), bv.x);
            as_[1][c + 1] = __fadd_rn(__fadd_rn(__fadd_rn(hi32(a1[0]), hi32(a1[1])), __fadd_rn(hi32(a1[2]), hi32(a1[3]))), bv.y);
        }
        __syncthreads();

        // ---- Phase 3: gates (fp32 transcendentals) ----
        if (tid < 512) {
            int b = tid >> 8, h = tid & (H - 1);
            int gb = gb0 + b;
            float gi = as_[b][h];
            float fl = as_[b][H + h];
            float fr = as_[b][2 * H + h];
            float go = as_[b][3 * H + h];
            float gc = as_[b][4 * H + h];
            float cl = g_states[gb][sL[b]][h];
            float cr = g_states[gb][sR[b]][h];
            float cc = sigf(fl) * cl + sigf(fr) * cr + sigf(gi) * tanhf(gc);
            float hp = sigf(go) * tanhf(cc);
            g_states[gb][sL[b]][h]     = cc;
            g_states[gb][sL[b]][H + h] = hp;
        }
        __syncthreads();

        // ---- Phase 3b: shift perm / logits (remove merged entry) ----
        {
            float rv = 0.0f; int havework = 0, kind = 0, wb = 0, wj = 0;
            if (tid < 384) {
                kind = (tid >= 192);
                int ii = kind ? (tid - 192) : tid;   // proper bijection [0,192)
                int b = (ii >= 96) ? 1 : 0;
                int j = ii - b * 96;
                int idx = selidx[b];
                if (!kind) {  // perm: new pm[j] = old pm[j+1] for idx+1..n-2
                    if (j >= idx + 1 && j <= n - 2) {
                        havework = 1; rv = __int_as_float(pm[b][j + 1]); wb = b; wj = j;
                    }
                } else {      // logits: new lg[j] = old lg[j+1] for idx+1..n-3
                    if (j >= idx + 1 && j <= n - 3) {
                        havework = 1; rv = lg[b][j + 1]; wb = b; wj = j;
                    }
                }
            }
            __syncthreads();
            if (havework) {
                if (!kind) pm[wb][wj] = __float_as_int(rv);
                else       lg[wb][wj] = rv;
            }
        }
        __syncthreads();

        // ---- Phase 4: stage sel inputs for the (up to) 2 new pairs per batch ----
        for (int i = tid; i < 4 * D; i += BD) {
            int pi = i >> 9, k = i & (D - 1);
            int b = pi >> 1, s = pi & 1;
            int q = selidx[b] - 1 + s;
            if (q >= 0 && q <= n - 3) {
                int slot = (k < H) ? pm[b][q] : pm[b][q + 1];
                int col  = (k < H) ? (H + k) : k;
                xsel[pi][k] = g_states[gb0 + b][slot][col];
            }
        }
        __syncthreads();

        // ---- Phase 5: new pair logits (4 pair-GEMVs, 128 cols each) ----
        if (tid < 512) {
            int pi = tid >> 7;
            int b = pi >> 1, s = pi & 1;
            int j = tid & 127;
            int q = selidx[b] - 1 + s;
            if (q >= 0 && q <= n - 3) {
                float y = pair_logit_partial(&xsel[pi][0], &xsel[pi][H], Ws1, bs1, Ws2, j);
                for (int o = 16; o; o >>= 1)
                    y = __fadd_rn(y, __shfl_xor_sync(0xffffffffu, y, o));
                if ((tid & 31) == 0) red[pi][(tid >> 5) & 3] = y;
            }
        }
        __syncthreads();
        if (tid < 4) {
            int b = tid >> 1, s = tid & 1;
            int q = selidx[b] - 1 + s;
            if (q >= 0 && q <= n - 3)
                lg[b][q] = __fadd_rn(
                    __fadd_rn(__fadd_rn(red[tid][0], red[tid][1]),
                              __fadd_rn(red[tid][2], red[tid][3])), bs2[0]);
        }
        __syncthreads();
    }

    // ---- root hidden ----
    for (int i = tid; i < 2 * H; i += BD) {
        int b = i >> 8, h = i & (H - 1);
        g_hroot[gb0 + b][h] = g_states[gb0 + b][pm[b][0]][H + h];
    }
}

// ======================================================================
// MLP as 3 column-parallel kernels (latency hidden by CTA parallelism)
// ======================================================================
__global__ void mlp_l1(const float* __restrict__ Wm1, const float* __restrict__ bm1) {
    __shared__ float hsh[H];
    int b = blockIdx.y;
    int c = blockIdx.x * 256 + threadIdx.x;
    if (threadIdx.x < H) hsh[threadIdx.x] = g_hroot[b][threadIdx.x];
    __syncthreads();
    float acc = bm1[c];
    const float* wp = Wm1 + c;
#pragma unroll 8
    for (int k = 0; k < H; k++)
        acc = __fmaf_rn(hsh[k], wp[k * MLPD], acc);
    g_x1[b][c] = fmaxf(acc, 0.0f);
}

__global__ void mlp_l2(const float* __restrict__ Wm2, const float* __restrict__ bm2) {
    __shared__ float x1s[MLPD];
    int b = blockIdx.y;
    int c = blockIdx.x * 256 + threadIdx.x;
    for (int i = threadIdx.x; i < MLPD; i += 256) x1s[i] = g_x1[b][i];
    __syncthreads();
    float acc = bm2[c];
    const float* wp = Wm2 + c;
#pragma unroll 8
    for (int k = 0; k < MLPD; k++)
        acc = __fmaf_rn(x1s[k], wp[k * MLPD], acc);
    g_x2[b][c] = fmaxf(acc, 0.0f);
}

__global__ void mlp_l3(const float* __restrict__ Wout, const float* __restrict__ bout,
                       float* __restrict__ out) {
    __shared__ float red[4][NC];
    int b = blockIdx.x;
    int tid = threadIdx.x;
    float p0 = 0.f, p1 = 0.f, p2 = 0.f;
    for (int k = tid; k < MLPD; k += 128) {
        float xv = g_x2[b][k];
        p0 = __fmaf_rn(xv, Wout[k * NC + 0], p0);
        p1 = __fmaf_rn(xv, Wout[k * NC + 1], p1);
        p2 = __fmaf_rn(xv, Wout[k * NC + 2], p2);
    }
    for (int o = 16; o; o >>= 1) {
        p0 += __shfl_xor_sync(0xffffffffu, p0, o);
        p1 += __shfl_xor_sync(0xffffffffu, p1, o);
        p2 += __shfl_xor_sync(0xffffffffu, p2, o);
    }
    int lane = tid & 31, wrp = tid >> 5;
    if (lane == 0) { red[wrp][0] = p0; red[wrp][1] = p1; red[wrp][2] = p2; }
    __syncthreads();
    if (tid < NC) {
        float s = bout[tid];
        for (int w = 0; w < 4; w++) s += red[w][tid];
        out[b * NC + tid] = s;
    }
}

// ======================================================================
extern "C" void kernel_launch(void* const* d_in, const int* in_sizes, int n_in,
                              void* d_out, int out_size) {
    const int*   sent = (const int*)d_in[0];
    // d_in[1] = transitions (unused by reference)
    const float* emb  = (const float*)d_in[2];
    const float* Wenc = (const float*)d_in[3];
    const float* benc = (const float*)d_in[4];
    const float* Wc   = (const float*)d_in[5];
    const float* bc   = (const float*)d_in[6];
    const float* Ws1  = (const float*)d_in[7];
    const float* bs1  = (const float*)d_in[8];
    const float* Ws2  = (const float*)d_in[9];
    const float* bs2  = (const float*)d_in[10];
    const float* Wm1  = (const float*)d_in[11];
    const float* bm1  = (const float*)d_in[12];
    const float* Wm2  = (const float*)d_in[13];
    const float* bm2  = (const float*)d_in[14];
    const float* Wout = (const float*)d_in[15];
    const float* bout = (const float*)d_in[16];

    encode_kernel<<<768, 128>>>(sent, emb, Wenc, benc);
    initsel_kernel<<<dim3(6, 64), 128>>>(Ws1, bs1, Ws2, bs2);
    scan_kernel<<<32, BD>>>(Wc, bc, Ws1, bs1, Ws2, bs2);
    mlp_l1<<<dim3(4, B), 256>>>(Wm1, bm1);
    mlp_l2<<<dim3(4, B), 256>>>(Wm2, bm2);
    mlp_l3<<<B, 128>>>(Wout, bout, (float*)d_out);
}

// round 6
// speedup vs baseline: 1.2550x; 1.2550x over previous
#include <cuda_runtime.h>
#include <math.h>

#define B   64
#define S   96
#define E   300
#define D   512
#define H   256
#define SEL 128
#define G5  1280   // 5*H
#define MLPD 1024
#define NC  3

#define CL  4      // cluster size
#define TPB 256    // threads per scan CTA

typedef unsigned long long ull;

// ---- static device scratch (no allocs allowed) ----
__device__ __align__(16) float g_states[B][S][D];     // 12.6 MB, L2-resident
__device__ float g_logits0[B][S - 1];
__device__ float g_hroot[B][H];
__device__ float g_x1[B][MLPD];
__device__ float g_x2[B][MLPD];
__device__ float g_newlg[B][2];

__device__ __forceinline__ float sigf(float x) { return 1.0f / (1.0f + expf(-x)); }

__device__ __forceinline__ ull fma2(ull a, ull b, ull c) {
    ull d;
    asm("fma.rn.f32x2 %0, %1, %2, %3;" : "=l"(d) : "l"(a), "l"(b), "l"(c));
    return d;
}
__device__ __forceinline__ ull pack2(float x, float y) {
    ull d;
    asm("mov.b64 %0, {%1, %2};" : "=l"(d) : "f"(x), "f"(y));
    return d;
}
__device__ __forceinline__ float lo32(ull v) { return __uint_as_float((unsigned)(v & 0xffffffffull)); }
__device__ __forceinline__ float hi32(ull v) { return __uint_as_float((unsigned)(v >> 32)); }

// full cluster barrier with cluster-scope fences on both sides
// (fence scope >= cluster => L1D invalidate, so post-sync global reads are fresh)
__device__ __forceinline__ void cluster_sync_full() {
    asm volatile("fence.acq_rel.cluster;" ::: "memory");
    asm volatile("barrier.cluster.arrive.aligned;" ::: "memory");
    asm volatile("barrier.cluster.wait.aligned;" ::: "memory");
    asm volatile("fence.acq_rel.cluster;" ::: "memory");
}

// Pair-logit partial used by initsel (initial 95 logits per batch).
__device__ __forceinline__ float pair_logit_partial(
    const float* __restrict__ hL, const float* __restrict__ hR,
    const float* __restrict__ Ws1, const float* __restrict__ bs1,
    const float* __restrict__ Ws2, int j)
{
    float a[8];
#pragma unroll
    for (int m = 0; m < 8; m++) a[m] = 0.0f;
    const float* wp = Ws1 + j;
    for (int k = 0; k < 64; k++) {
#pragma unroll
        for (int m = 0; m < 4; m++)
            a[m] = __fmaf_rn(hL[m * 64 + k], wp[(m * 64 + k) * SEL], a[m]);
#pragma unroll
        for (int m = 0; m < 4; m++)
            a[4 + m] = __fmaf_rn(hR[m * 64 + k], wp[(256 + m * 64 + k) * SEL], a[4 + m]);
    }
    float s = a[0] + a[1] + a[2] + a[3] + a[4] + a[5] + a[6] + a[7] + bs1[j];
    return tanhf(s) * Ws2[j];
}

// ======================================================================
// Kernel 1: encode
// ======================================================================
__global__ void encode_kernel(const int* __restrict__ sent,
                              const float* __restrict__ emb,
                              const float* __restrict__ Wenc,
                              const float* __restrict__ benc) {
    __shared__ float xs[8][E];
    __shared__ int tok[8];
    int row0 = blockIdx.x * 8;
    int tid = threadIdx.x;
    if (tid < 8) tok[tid] = sent[row0 + tid];
    __syncthreads();
    for (int i = tid; i < 8 * E; i += 128) {
        int r = i / E, k = i - r * E;
        xs[r][k] = emb[(long)tok[r] * E + k];
    }
    __syncthreads();
    int c = tid * 4;
    float4 acc[8];
#pragma unroll
    for (int r = 0; r < 8; r++) acc[r] = make_float4(0.f, 0.f, 0.f, 0.f);
    for (int k = 0; k < E; k++) {
        float4 w = *(const float4*)&Wenc[k * D + c];
#pragma unroll
        for (int r = 0; r < 8; r++) {
            float xv = xs[r][k];
            acc[r].x = __fmaf_rn(xv, w.x, acc[r].x);
            acc[r].y = __fmaf_rn(xv, w.y, acc[r].y);
            acc[r].z = __fmaf_rn(xv, w.z, acc[r].z);
            acc[r].w = __fmaf_rn(xv, w.w, acc[r].w);
        }
    }
    float4 bv = *(const float4*)&benc[c];
#pragma unroll
    for (int r = 0; r < 8; r++) {
        acc[r].x += bv.x; acc[r].y += bv.y; acc[r].z += bv.z; acc[r].w += bv.w;
        int gr = row0 + r;
        int b = gr / S, s = gr - b * S;
        *(float4*)&g_states[b][s][c] = acc[r];
    }
}

// ======================================================================
// Kernel 2: initial pair logits (95 per batch)
// ======================================================================
__global__ void initsel_kernel(const float* __restrict__ Ws1,
                               const float* __restrict__ bs1,
                               const float* __restrict__ Ws2,
                               const float* __restrict__ bs2) {
    __shared__ float hs[17][H];
    __shared__ float red[4];
    int b = blockIdx.y;
    int p0 = blockIdx.x * 16;
    int tid = threadIdx.x;
    int nrows = min(17, S - p0);
    for (int i = tid; i < nrows * H; i += 128) {
        int r = i >> 8, k = i & (H - 1);
        hs[r][k] = g_states[b][p0 + r][H + k];
    }
    __syncthreads();
    int npairs = min(16, (S - 1) - p0);
    for (int p = 0; p < npairs; p++) {
        float y = pair_logit_partial(hs[p], hs[p + 1], Ws1, bs1, Ws2, tid);
        for (int o = 16; o; o >>= 1)
            y += __shfl_xor_sync(0xffffffffu, y, o);
        if ((tid & 31) == 0) red[tid >> 5] = y;
        __syncthreads();
        if (tid == 0)
            g_logits0[b][p0 + p] = red[0] + red[1] + red[2] + red[3] + bs2[0];
        __syncthreads();
    }
}

// ======================================================================
// Kernel 3: the scan. 64 CTAs as 16 clusters of 4.
// Cluster owns 4 batches; CTA r owns gate columns for h in [64r, 64r+64).
// ======================================================================
__global__ void __cluster_dims__(CL, 1, 1) __launch_bounds__(TPB, 1)
scan_kernel(const float* __restrict__ Wc,  const float* __restrict__ bc,
            const float* __restrict__ Ws1, const float* __restrict__ bs1,
            const float* __restrict__ Ws2, const float* __restrict__ bs2) {
    __shared__ __align__(16) ull   xs2[4][D];      // (x,x) packed per batch
    __shared__ __align__(16) ull   xpel[D];        // (pairA, pairB) packed, own batch
    __shared__ __align__(16) ull   p5[2][SEL];     // phase-5 k-half partials
    __shared__ __align__(16) float sgate[4][5][64];
    __shared__ float lg[4][S];
    __shared__ int   pm[4][S];
    __shared__ float amaxv[4][2];
    __shared__ int   amaxi_[4][2];
    __shared__ int   selidx[4], sLs[4], sRs[4];
    __shared__ float red5[2][4];

    int tid = threadIdx.x;
    int r   = blockIdx.x & (CL - 1);        // rank in cluster
    int gb0 = blockIdx.x & ~(CL - 1);       // first batch of cluster (4 per cluster)

    // replicated init of lg / pm
    for (int i = tid; i < 4 * (S - 1); i += TPB) {
        int b = i / (S - 1), j = i - b * (S - 1);
        lg[b][j] = g_logits0[gb0 + b][j];
    }
    for (int i = tid; i < 4 * S; i += TPB) {
        int b = i / S, j = i - b * S;
        pm[b][j] = j;
    }
    __syncthreads();

    for (int t = 0; t < S - 1; t++) {
        int n = S - t;
        int np = n - 1;

        // ---- argmax (replicated; 64 threads per batch) ----
        {
            int b = tid >> 6, lt = tid & 63;
            float best = -1e30f; int bi = 0;
            for (int j = lt; j < np; j += 64) {
                float v = lg[b][j];
                if (v > best) { best = v; bi = j; }
            }
            for (int o = 16; o; o >>= 1) {
                float ov = __shfl_xor_sync(0xffffffffu, best, o);
                int   oi = __shfl_xor_sync(0xffffffffu, bi, o);
                if (ov > best || (ov == best && oi < bi)) { best = ov; bi = oi; }
            }
            if ((lt & 31) == 0) { amaxv[b][lt >> 5] = best; amaxi_[b][lt >> 5] = bi; }
        }
        __syncthreads();
        if (tid < 4) {
            int b = tid;
            float v0 = amaxv[b][0], v1 = amaxv[b][1];
            int   i0 = amaxi_[b][0], i1 = amaxi_[b][1];
            int bi = (v1 > v0 || (v1 == v0 && i1 < i0)) ? i1 : i0;
            selidx[b] = bi;
            sLs[b] = pm[b][bi];
            sRs[b] = pm[b][bi + 1];
        }
        __syncthreads();

        // ---- xs staging: packed (x,x) for all 4 batches ----
        for (int i = tid; i < 4 * D; i += TPB) {
            int b = i >> 9, k = i & (D - 1);
            int slot = (k < H) ? sLs[b] : sRs[b];
            int col  = (k < H) ? (H + k) : k;
            float xv = g_states[gb0 + b][slot][col];
            xs2[b][k] = pack2(xv, xv);
        }
        // all CTAs must finish READING old states before any CTA overwrites
        cluster_sync_full();                                     // SYNC 0

        // ---- compose: 160 threads, 2 cols x 4 batches each ----
        if (tid < 160) {
            int g = tid >> 5, u2 = (tid & 31) << 1;
            int c = g * 256 + r * 64 + u2;
            ull bias = pack2(bc[c], bc[c + 1]);
            ull a0 = bias, a1 = bias, a2 = bias, a3 = bias;
            const float* wp = Wc + c;
#pragma unroll 4
            for (int k = 0; k < D; k += 2) {
                ull w0 = *(const ull*)(wp + (size_t)k * G5);
                ull w1 = *(const ull*)(wp + (size_t)(k + 1) * G5);
                ulonglong2 x0 = *(const ulonglong2*)&xs2[0][k];
                ulonglong2 x1 = *(const ulonglong2*)&xs2[1][k];
                ulonglong2 x2 = *(const ulonglong2*)&xs2[2][k];
                ulonglong2 x3 = *(const ulonglong2*)&xs2[3][k];
                a0 = fma2(w0, x0.x, a0); a0 = fma2(w1, x0.y, a0);
                a1 = fma2(w0, x1.x, a1); a1 = fma2(w1, x1.y, a1);
                a2 = fma2(w0, x2.x, a2); a2 = fma2(w1, x2.y, a2);
                a3 = fma2(w0, x3.x, a3); a3 = fma2(w1, x3.y, a3);
            }
            *(ull*)&sgate[0][g][u2] = a0;
            *(ull*)&sgate[1][g][u2] = a1;
            *(ull*)&sgate[2][g][u2] = a2;
            *(ull*)&sgate[3][g][u2] = a3;
        }
        __syncthreads();

        // ---- gates for h in [64r, 64r+64), all 4 batches ----
        {
            int b = tid >> 6, u = tid & 63;
            int h = r * 64 + u;
            int gb = gb0 + b;
            float gi = sgate[b][0][u];
            float fl = sgate[b][1][u];
            float fr = sgate[b][2][u];
            float go = sgate[b][3][u];
            float gc = sgate[b][4][u];
            float cl = g_states[gb][sLs[b]][h];
            float cr = g_states[gb][sRs[b]][h];
            float cc = sigf(fl) * cl + sigf(fr) * cr + sigf(gi) * tanhf(gc);
            float hp = sigf(go) * tanhf(cc);
            g_states[gb][sLs[b]][h]     = cc;
            g_states[gb][sLs[b]][H + h] = hp;
        }
        // state updates must be cluster-visible before phase 4/5 reads
        cluster_sync_full();                                     // SYNC 1

        // ---- shift pm / lg locally (replicated) ----
        {
            int i0 = tid, i1 = tid + TPB;
            int b0 = i0 / 96, j0 = i0 - b0 * 96;
            float pv0 = 0.f, lv0 = 0.f; int wp0 = 0, wl0 = 0;
            {
                int idx = selidx[b0];
                if (j0 >= idx + 1 && j0 <= n - 2) { pv0 = __int_as_float(pm[b0][j0 + 1]); wp0 = 1; }
                if (j0 >= idx + 1 && j0 <= n - 3) { lv0 = lg[b0][j0 + 1]; wl0 = 1; }
            }
            int b1 = 0, j1 = 0; float pv1 = 0.f, lv1 = 0.f; int wp1 = 0, wl1 = 0;
            if (i1 < 384) {
                b1 = i1 / 96; j1 = i1 - b1 * 96;
                int idx = selidx[b1];
                if (j1 >= idx + 1 && j1 <= n - 2) { pv1 = __int_as_float(pm[b1][j1 + 1]); wp1 = 1; }
                if (j1 >= idx + 1 && j1 <= n - 3) { lv1 = lg[b1][j1 + 1]; wl1 = 1; }
            }
            __syncthreads();
            if (wp0) pm[b0][j0] = __float_as_int(pv0);
            if (wl0) lg[b0][j0] = lv0;
            if (wp1) pm[b1][j1] = __float_as_int(pv1);
            if (wl1) lg[b1][j1] = lv1;
        }
        __syncthreads();

        // ---- xsel staging: own batch (gb0+r), both new pairs packed ----
        {
            int idx = selidx[r];
            int q0 = idx - 1, q1 = idx;
            bool vA = (q0 >= 0) && (q0 <= n - 3);
            bool vB = (q1 <= n - 3);
            for (int k = tid; k < D; k += TPB) {
                int col = (k < H) ? (H + k) : k;
                float xA = 0.f, xB = 0.f;
                if (vA) xA = g_states[gb0 + r][(k < H) ? pm[r][q0] : pm[r][q0 + 1]][col];
                if (vB) xB = g_states[gb0 + r][(k < H) ? pm[r][q1] : pm[r][q1 + 1]][col];
                xpel[k] = pack2(xA, xB);
            }
        }
        __syncthreads();

        // ---- phase 5: own batch's 2 pair logits (k split over 2 halves) ----
        {
            int j = tid & 127, kh = tid >> 7;
            const float* wp = Ws1 + j;
            ull acc0 = 0ull, acc1 = 0ull;
            int k0 = kh << 8;
#pragma unroll 8
            for (int k = k0; k < k0 + 256; k += 2) {
                float w0 = wp[(size_t)k * SEL];
                float w1 = wp[(size_t)(k + 1) * SEL];
                ulonglong2 xv = *(const ulonglong2*)&xpel[k];
                acc0 = fma2(pack2(w0, w0), xv.x, acc0);
                acc1 = fma2(pack2(w1, w1), xv.y, acc1);
            }
            p5[kh][j] = pack2(lo32(acc0) + lo32(acc1), hi32(acc0) + hi32(acc1));
        }
        __syncthreads();
        if (tid < 128) {
            int j = tid;
            ull u0 = p5[0][j], u1 = p5[1][j];
            float sA = lo32(u0) + lo32(u1) + bs1[j];
            float sB = hi32(u0) + hi32(u1) + bs1[j];
            float yA = tanhf(sA) * Ws2[j];
            float yB = tanhf(sB) * Ws2[j];
            for (int o = 16; o; o >>= 1) {
                yA += __shfl_xor_sync(0xffffffffu, yA, o);
                yB += __shfl_xor_sync(0xffffffffu, yB, o);
            }
            if ((j & 31) == 0) { red5[0][j >> 5] = yA; red5[1][j >> 5] = yB; }
        }
        __syncthreads();
        if (tid < 2) {
            g_newlg[gb0 + r][tid] =
                red5[tid][0] + red5[tid][1] + red5[tid][2] + red5[tid][3] + bs2[0];
        }
        // new logits must be cluster-visible
        cluster_sync_full();                                     // SYNC 2

        // ---- update local lg replicas from all 4 batches ----
        if (tid < 8) {
            int b = tid >> 1, s = tid & 1;
            int q = selidx[b] - 1 + s;
            if (q >= 0 && q <= n - 3)
                lg[b][q] = g_newlg[gb0 + b][s];
        }
        __syncthreads();
    }

    // ---- root hidden: own h-range, all 4 batches ----
    {
        int b = tid >> 6, u = tid & 63;
        int h = r * 64 + u;
        g_hroot[gb0 + b][h] = g_states[gb0 + b][pm[b][0]][H + h];
    }
}

// ======================================================================
// MLP as 3 column-parallel kernels
// ======================================================================
__global__ void mlp_l1(const float* __restrict__ Wm1, const float* __restrict__ bm1) {
    __shared__ float hsh[H];
    int b = blockIdx.y;
    int c = blockIdx.x * 256 + threadIdx.x;
    if (threadIdx.x < H) hsh[threadIdx.x] = g_hroot[b][threadIdx.x];
    __syncthreads();
    float acc = bm1[c];
    const float* wp = Wm1 + c;
#pragma unroll 8
    for (int k = 0; k < H; k++)
        acc = __fmaf_rn(hsh[k], wp[k * MLPD], acc);
    g_x1[b][c] = fmaxf(acc, 0.0f);
}

__global__ void mlp_l2(const float* __restrict__ Wm2, const float* __restrict__ bm2) {
    __shared__ float x1s[MLPD];
    int b = blockIdx.y;
    int c = blockIdx.x * 256 + threadIdx.x;
    for (int i = threadIdx.x; i < MLPD; i += 256) x1s[i] = g_x1[b][i];
    __syncthreads();
    float acc = bm2[c];
    const float* wp = Wm2 + c;
#pragma unroll 8
    for (int k = 0; k < MLPD; k++)
        acc = __fmaf_rn(x1s[k], wp[k * MLPD], acc);
    g_x2[b][c] = fmaxf(acc, 0.0f);
}

__global__ void mlp_l3(const float* __restrict__ Wout, const float* __restrict__ bout,
                       float* __restrict__ out) {
    __shared__ float red[4][NC];
    int b = blockIdx.x;
    int tid = threadIdx.x;
    float p0 = 0.f, p1 = 0.f, p2 = 0.f;
    for (int k = tid; k < MLPD; k += 128) {
        float xv = g_x2[b][k];
        p0 = __fmaf_rn(xv, Wout[k * NC + 0], p0);
        p1 = __fmaf_rn(xv, Wout[k * NC + 1], p1);
        p2 = __fmaf_rn(xv, Wout[k * NC + 2], p2);
    }
    for (int o = 16; o; o >>= 1) {
        p0 += __shfl_xor_sync(0xffffffffu, p0, o);
        p1 += __shfl_xor_sync(0xffffffffu, p1, o);
        p2 += __shfl_xor_sync(0xffffffffu, p2, o);
    }
    int lane = tid & 31, wrp = tid >> 5;
    if (lane == 0) { red[wrp][0] = p0; red[wrp][1] = p1; red[wrp][2] = p2; }
    __syncthreads();
    if (tid < NC) {
        float s = bout[tid];
        for (int w = 0; w < 4; w++) s += red[w][tid];
        out[b * NC + tid] = s;
    }
}

// ======================================================================
extern "C" void kernel_launch(void* const* d_in, const int* in_sizes, int n_in,
                              void* d_out, int out_size) {
    const int*   sent = (const int*)d_in[0];
    // d_in[1] = transitions (unused by reference)
    const float* emb  = (const float*)d_in[2];
    const float* Wenc = (const float*)d_in[3];
    const float* benc = (const float*)d_in[4];
    const float* Wc   = (const float*)d_in[5];
    const float* bc   = (const float*)d_in[6];
    const float* Ws1  = (const float*)d_in[7];
    const float* bs1  = (const float*)d_in[8];
    const float* Ws2  = (const float*)d_in[9];
    const float* bs2  = (const float*)d_in[10];
    const float* Wm1  = (const float*)d_in[11];
    const float* bm1  = (const float*)d_in[12];
    const float* Wm2  = (const float*)d_in[13];
    const float* bm2  = (const float*)d_in[14];
    const float* Wout = (const float*)d_in[15];
    const float* bout = (const float*)d_in[16];

    encode_kernel<<<768, 128>>>(sent, emb, Wenc, benc);
    initsel_kernel<<<dim3(6, 64), 128>>>(Ws1, bs1, Ws2, bs2);
    scan_kernel<<<64, TPB>>>(Wc, bc, Ws1, bs1, Ws2, bs2);
    mlp_l1<<<dim3(4, B), 256>>>(Wm1, bm1);
    mlp_l2<<<dim3(4, B), 256>>>(Wm2, bm2);
    mlp_l3<<<B, 128>>>(Wout, bout, (float*)d_out);
}